// round 2
// baseline (speedup 1.0000x reference)
#include <cuda_runtime.h>

#define CPB 128        // cells per block == threads per block
#define DD  30         // features per cell: B*5 + C = 2*5 + 20
#define CC  20         // classes
#define NB  2          // boxes
#define LAMBDA_NOOBJ 0.5f

__device__ double       g_acc;    // zero-initialized at module load; reset by last block
__device__ unsigned int g_count;  // ditto

__global__ __launch_bounds__(CPB) void yolo_loss_kernel(
    const float* __restrict__ preds,
    const float* __restrict__ targets,
    long long n_cells,
    unsigned int n_blocks,
    float invN,
    float* __restrict__ out)
{
    __shared__ float sp[CPB * DD];
    __shared__ float st[CPB * DD];

    const int tid = threadIdx.x;
    const long long base = (long long)blockIdx.x * CPB;

    if (base + CPB <= n_cells) {
        // Full block: fully coalesced float4 staging.
        // base*DD floats = blockIdx*3840 floats -> 16B-aligned offset.
        const float4* gp = reinterpret_cast<const float4*>(preds   + base * DD);
        const float4* gt = reinterpret_cast<const float4*>(targets + base * DD);
        float4* sp4 = reinterpret_cast<float4*>(sp);
        float4* st4 = reinterpret_cast<float4*>(st);
        #pragma unroll
        for (int i = tid; i < CPB * DD / 4; i += CPB) {
            sp4[i] = gp[i];
            st4[i] = gt[i];
        }
    } else {
        // Tail block: guarded scalar staging.
        const int nf = (int)(n_cells - base) * DD;
        for (int i = tid; i < nf; i += CPB) {
            sp[i] = preds[base * DD + i];
            st[i] = targets[base * DD + i];
        }
    }
    __syncthreads();

    float loss = 0.0f;
    const long long cell = base + tid;
    if (cell < n_cells) {
        const float* p = sp + tid * DD;
        const float* t = st + tid * DD;

        // IoU for each of the NB boxes
        float iou[NB];
        #pragma unroll
        for (int b = 0; b < NB; b++) {
            const float x1 = p[b*5+0], y1 = p[b*5+1], w1 = p[b*5+2], h1 = p[b*5+3];
            const float x2 = t[b*5+0], y2 = t[b*5+1], w2 = t[b*5+2], h2 = t[b*5+3];
            const float tlx = fmaxf(x1 - w1 * 0.5f, x2 - w2 * 0.5f);
            const float tly = fmaxf(y1 - h1 * 0.5f, y2 - h2 * 0.5f);
            const float brx = fminf(x1 + w1 * 0.5f, x2 + w2 * 0.5f);
            const float bry = fminf(y1 + h1 * 0.5f, y2 + h2 * 0.5f);
            const float iw = fmaxf(0.0f, brx - tlx);
            const float ih = fmaxf(0.0f, bry - tly);
            const float inter = iw * ih;
            const float uni = w1 * h1 + w2 * h2 - inter;
            iou[b] = inter / uni;
        }
        // argmax over boxes, first-max tie break (strict >)
        const int bi = (iou[1] > iou[0]) ? 1 : 0;

        // class loss + argmax of target classes + has_obj
        float cls = 0.0f;
        float maxtc = t[10];
        int gnd = 0;
        bool has_obj = false;
        #pragma unroll
        for (int j = 0; j < CC; j++) {
            const float pc = p[10 + j];
            const float tc = t[10 + j];
            const float d = pc - tc;
            cls += d * d;
            if (tc != 0.0f) has_obj = true;
            if (tc > maxtc) { maxtc = tc; gnd = j; }
        }
        const float pg = p[10 + gnd];

        // position loss on the best box
        const float dx = p[bi*5+0] - t[bi*5+0];
        const float dy = p[bi*5+1] - t[bi*5+1];
        const float pos = has_obj ? (dx * dx + dy * dy) : 0.0f;

        // confidence loss
        float conf = 0.0f;
        #pragma unroll
        for (int b = 0; b < NB; b++) {
            const float cd = iou[b] * pg - iou[b];          // ious*pg - ious, literal
            const float w  = (b == bi) ? 1.0f : LAMBDA_NOOBJ;
            conf += w * cd * cd;
        }

        loss = pos + cls + conf;
    }

    // block reduction: warp shuffle -> smem -> one double atomic per block
    #pragma unroll
    for (int o = 16; o > 0; o >>= 1)
        loss += __shfl_down_sync(0xffffffffu, loss, o);

    __shared__ float wsum[CPB / 32];
    __shared__ bool  is_last;
    if ((tid & 31) == 0) wsum[tid >> 5] = loss;
    __syncthreads();

    if (tid == 0) {
        float s = 0.0f;
        #pragma unroll
        for (int i = 0; i < CPB / 32; i++) s += wsum[i];
        atomicAdd(&g_acc, (double)s);
        __threadfence();
        const unsigned int prev = atomicAdd(&g_count, 1u);
        is_last = (prev == n_blocks - 1u);
    }
    __syncthreads();

    if (is_last && tid == 0) {
        // All other blocks' atomics are visible (fence + atomic ordering).
        out[0] = (float)(g_acc * (double)invN);
        // Reset for next graph replay (deterministic across calls).
        g_acc   = 0.0;
        __threadfence();
        g_count = 0u;
    }
}

extern "C" void kernel_launch(void* const* d_in, const int* in_sizes, int n_in,
                              void* d_out, int out_size)
{
    const float* preds   = (const float*)d_in[0];
    const float* targets = (const float*)d_in[1];

    const long long n_cells = (long long)in_sizes[0] / DD;   // N*S*S
    const long long N = n_cells / 49;                         // S=7

    const unsigned int grid = (unsigned int)((n_cells + CPB - 1) / CPB);
    yolo_loss_kernel<<<grid, CPB>>>(preds, targets, n_cells, grid,
                                    1.0f / (float)N, (float*)d_out);
}

// round 3
// speedup vs baseline: 1.2104x; 1.2104x over previous
#include <cuda_runtime.h>
#include <cstdint>

#define CPB 128        // cells per block == threads per block
#define DD  30         // features per cell: B*5 + C = 2*5 + 20
#define CC  20         // classes
#define NB  2          // boxes
#define LAMBDA_NOOBJ 0.5f

#define TILE_BYTES (CPB * DD * 4)   // 15360 per array

__device__ double       g_acc;    // zero at load; reset by last block each run
__device__ unsigned int g_count;  // ditto

__device__ __forceinline__ uint32_t smem_u32(const void* p) {
    uint32_t a;
    asm("{ .reg .u64 t; cvta.to.shared.u64 t, %1; cvt.u32.u64 %0, t; }"
        : "=r"(a) : "l"(p));
    return a;
}

__global__ __launch_bounds__(CPB) void yolo_loss_kernel(
    const float* __restrict__ preds,
    const float* __restrict__ targets,
    long long n_cells,
    unsigned int n_blocks,
    float invN,
    float* __restrict__ out)
{
    __shared__ __align__(128) float sp[CPB * DD];
    __shared__ __align__(128) float st[CPB * DD];
    __shared__ __align__(8)   uint64_t mbar;

    const int tid = threadIdx.x;
    const long long base = (long long)blockIdx.x * CPB;

    if (base + CPB <= n_cells) {
        // Full block: bulk async copy (TMA/UBLKCP path) — no register staging,
        // full 30 KB in flight per block immediately.
        const uint32_t mb = smem_u32(&mbar);
        if (tid == 0) {
            asm volatile("mbarrier.init.shared.b64 [%0], %1;" :: "r"(mb), "r"(1u) : "memory");
            asm volatile("fence.proxy.async.shared::cta;" ::: "memory");
            asm volatile("mbarrier.arrive.expect_tx.shared.b64 _, [%0], %1;"
                         :: "r"(mb), "r"(2u * TILE_BYTES) : "memory");
            asm volatile("cp.async.bulk.shared::cta.global.mbarrier::complete_tx::bytes "
                         "[%0], [%1], %2, [%3];"
                         :: "r"(smem_u32(sp)), "l"(preds + base * DD),
                            "r"((uint32_t)TILE_BYTES), "r"(mb) : "memory");
            asm volatile("cp.async.bulk.shared::cta.global.mbarrier::complete_tx::bytes "
                         "[%0], [%1], %2, [%3];"
                         :: "r"(smem_u32(st)), "l"(targets + base * DD),
                            "r"((uint32_t)TILE_BYTES), "r"(mb) : "memory");
        }
        __syncthreads();   // mbarrier.init visible to all before anyone waits
        // Wait for copy completion (parity 0, fresh barrier each launch).
        uint32_t done;
        do {
            asm volatile(
                "{\n\t.reg .pred p;\n\t"
                "mbarrier.try_wait.parity.acquire.cta.shared::cta.b64 p, [%1], %2, 0x989680;\n\t"
                "selp.b32 %0, 1, 0, p;\n\t}"
                : "=r"(done) : "r"(mb), "r"(0u) : "memory");
        } while (!done);
    } else {
        // Tail block (not hit for these shapes): guarded scalar staging.
        const int nf = (int)(n_cells - base) * DD;
        for (int i = tid; i < nf; i += CPB) {
            sp[i] = preds[base * DD + i];
            st[i] = targets[base * DD + i];
        }
        __syncthreads();
    }

    float loss = 0.0f;
    const long long cell = base + tid;
    if (cell < n_cells) {
        const float* p = sp + tid * DD;
        const float* t = st + tid * DD;

        // IoU for each of the NB boxes
        float iou[NB];
        #pragma unroll
        for (int b = 0; b < NB; b++) {
            const float x1 = p[b*5+0], y1 = p[b*5+1], w1 = p[b*5+2], h1 = p[b*5+3];
            const float x2 = t[b*5+0], y2 = t[b*5+1], w2 = t[b*5+2], h2 = t[b*5+3];
            const float tlx = fmaxf(x1 - w1 * 0.5f, x2 - w2 * 0.5f);
            const float tly = fmaxf(y1 - h1 * 0.5f, y2 - h2 * 0.5f);
            const float brx = fminf(x1 + w1 * 0.5f, x2 + w2 * 0.5f);
            const float bry = fminf(y1 + h1 * 0.5f, y2 + h2 * 0.5f);
            const float iw = fmaxf(0.0f, brx - tlx);
            const float ih = fmaxf(0.0f, bry - tly);
            const float inter = iw * ih;
            const float uni = w1 * h1 + w2 * h2 - inter;
            iou[b] = inter / uni;
        }
        // argmax over boxes, first-max tie break (strict >)
        const int bi = (iou[1] > iou[0]) ? 1 : 0;

        // class loss + argmax of target classes + has_obj
        float cls = 0.0f;
        float maxtc = t[10];
        int gnd = 0;
        bool has_obj = false;
        #pragma unroll
        for (int j = 0; j < CC; j++) {
            const float pc = p[10 + j];
            const float tc = t[10 + j];
            const float d = pc - tc;
            cls += d * d;
            if (tc != 0.0f) has_obj = true;
            if (tc > maxtc) { maxtc = tc; gnd = j; }
        }
        const float pg = p[10 + gnd];

        // position loss on the best box
        const float dx = p[bi*5+0] - t[bi*5+0];
        const float dy = p[bi*5+1] - t[bi*5+1];
        const float pos = has_obj ? (dx * dx + dy * dy) : 0.0f;

        // confidence loss
        float conf = 0.0f;
        #pragma unroll
        for (int b = 0; b < NB; b++) {
            const float cd = iou[b] * pg - iou[b];          // ious*pg - ious, literal
            const float w  = (b == bi) ? 1.0f : LAMBDA_NOOBJ;
            conf += w * cd * cd;
        }

        loss = pos + cls + conf;
    }

    // block reduction: warp shuffle -> smem -> one double atomic per block
    #pragma unroll
    for (int o = 16; o > 0; o >>= 1)
        loss += __shfl_down_sync(0xffffffffu, loss, o);

    __shared__ float wsum[CPB / 32];
    __shared__ bool  is_last;
    if ((tid & 31) == 0) wsum[tid >> 5] = loss;
    __syncthreads();

    if (tid == 0) {
        float s = 0.0f;
        #pragma unroll
        for (int i = 0; i < CPB / 32; i++) s += wsum[i];
        atomicAdd(&g_acc, (double)s);
        __threadfence();
        const unsigned int prev = atomicAdd(&g_count, 1u);
        is_last = (prev == n_blocks - 1u);
    }
    __syncthreads();

    if (is_last && tid == 0) {
        out[0] = (float)(g_acc * (double)invN);
        // Reset for next graph replay (deterministic across calls).
        g_acc   = 0.0;
        __threadfence();
        g_count = 0u;
    }
}

extern "C" void kernel_launch(void* const* d_in, const int* in_sizes, int n_in,
                              void* d_out, int out_size)
{
    const float* preds   = (const float*)d_in[0];
    const float* targets = (const float*)d_in[1];

    const long long n_cells = (long long)in_sizes[0] / DD;   // N*S*S
    const long long N = n_cells / 49;                         // S=7

    const unsigned int grid = (unsigned int)((n_cells + CPB - 1) / CPB);
    yolo_loss_kernel<<<grid, CPB>>>(preds, targets, n_cells, grid,
                                    1.0f / (float)N, (float*)d_out);
}